// round 8
// baseline (speedup 1.0000x reference)
#include <cuda_runtime.h>
#include <cstdint>
#include <cstring>

#define HH 32      // neighbors (== warp size)
#define LLL 4
#define CCC 64
#define CMID 8
#define COUT 64

// ---------------- cp.async helpers ----------------
__device__ __forceinline__ void cpa16(void* dst, const void* src) {
    unsigned d = (unsigned)__cvta_generic_to_shared(dst);
    asm volatile("cp.async.cg.shared.global [%0], [%1], 16;" :: "r"(d), "l"(src));
}
__device__ __forceinline__ void cpa_commit() { asm volatile("cp.async.commit_group;"); }
template<int K> __device__ __forceinline__ void cpa_wait() {
    asm volatile("cp.async.wait_group %0;" :: "n"(K));
}

__device__ __forceinline__ void ffma2(unsigned long long& acc,
                                      unsigned long long a, unsigned long long b) {
    asm("fma.rn.f32x2 %0, %1, %2, %0;" : "+l"(acc) : "l"(a), "l"(b));
}
__device__ __forceinline__ float2 unpack2(unsigned long long v) {
    float2 f; memcpy(&f, &v, 8); return f;
}
__device__ __forceinline__ ulonglong2 pack4(float4 v) {
    ulonglong2 u; memcpy(&u, &v, 16); return u;
}

// Stage one 1KB tile. Source chunk k (16B) -> smem slot (k>>1) + ((k&1)<<5).
// Consumer: lane i reads slots i and i+32 = floats [8i, 8i+8)  (conflict-free).
__device__ __forceinline__ void stage_issue(float4* b, const float* src, int lane) {
    const int k2 = lane + 32;
    cpa16(b + ((lane >> 1) + ((lane & 1) << 5)), src + lane * 4);
    cpa16(b + ((k2 >> 1) + ((k2 & 1) << 5)),     src + k2 * 4);
    cpa_commit();
}

// 3-round keep/send butterfly over 8-lane groups: lane (g*8+q) ends with
// sum over its group of v[q].
__device__ __forceinline__ float reduce8(const float* v, int q) {
    const unsigned FULL = 0xffffffffu;
    bool s4 = (q & 4) != 0;
    float a0 = (s4 ? v[4] : v[0]) + __shfl_xor_sync(FULL, s4 ? v[0] : v[4], 4);
    float a1 = (s4 ? v[5] : v[1]) + __shfl_xor_sync(FULL, s4 ? v[1] : v[5], 4);
    float a2 = (s4 ? v[6] : v[2]) + __shfl_xor_sync(FULL, s4 ? v[2] : v[6], 4);
    float a3 = (s4 ? v[7] : v[3]) + __shfl_xor_sync(FULL, s4 ? v[3] : v[7], 4);
    bool s2 = (q & 2) != 0;
    float b0c = (s2 ? a2 : a0) + __shfl_xor_sync(FULL, s2 ? a0 : a2, 2);
    float b1c = (s2 ? a3 : a1) + __shfl_xor_sync(FULL, s2 ? a1 : a3, 2);
    bool s1 = (q & 1) != 0;
    return (s1 ? b1c : b0c) + __shfl_xor_sync(FULL, s1 ? b0c : b1c, 1);
}

// Per-lane 8x8 GEMM panel: partials for all 8 m rows over this lane's 8 floats.
__device__ __forceinline__ void gemm8(const unsigned long long* wb,
                                      ulonglong2 u0, ulonglong2 u1, float* vals) {
    #pragma unroll
    for (int m2 = 0; m2 < 8; m2++) {
        unsigned long long am = 0ull;
        ffma2(am, u0.x, wb[m2 * 4 + 0]);
        ffma2(am, u0.y, wb[m2 * 4 + 1]);
        ffma2(am, u1.x, wb[m2 * 4 + 2]);
        ffma2(am, u1.y, wb[m2 * 4 + 3]);
        float2 f = unpack2(am);
        vals[m2] = f.x + f.y;
    }
}

__global__ __launch_bounds__(256, 2)
void tp_kernel(const float* __restrict__ s_points,
               const float* __restrict__ nbr_points,
               const float* __restrict__ s_feats,
               const float* __restrict__ nbr_feats,
               const float* __restrict__ W_in,
               const float* __restrict__ W_out,
               const float* __restrict__ w_m0,
               const float* __restrict__ w_m1,
               float* __restrict__ res, int N)
{
    __shared__ float4 sNF[8][3 * 64];     // per-warp TRIPLE-buffered 1KB tiles (24KB)
    __shared__ float4 sBUT[8][HH * 4];    // per-warp folded Wigner tables (16KB)
    __shared__ float4 sWoutT[CMID * 16];  // W_out^T, even/odd split per row (2KB)

    const int tid  = threadIdx.x;
    const int wid  = tid >> 5;
    const int lane = tid & 31;
    const int l    = lane >> 3;   // 0..3
    const int q    = lane & 7;    // 0..7
    const unsigned FULL = 0xffffffffu;

    // Stage W_out transposed + split-swizzled: value W_out[o][mm] -> row mm,
    // float4 f=o>>2 stored at slot (f>>1)+((f&1)<<3), float pos o&3.
    {
        float* wt = reinterpret_cast<float*>(sWoutT);
        for (int i = tid; i < COUT * CMID; i += 256) {
            int o = i >> 3, mm = i & 7;
            int f = o >> 2;
            int slot = (f >> 1) + ((f & 1) << 3);
            wt[mm * 64 + slot * 4 + (o & 3)] = W_out[i];
        }
    }
    __syncthreads();

    const int n = blockIdx.x * 8 + wid;
    if (n >= N) return;   // whole warp; no block syncs below

    const float w00 = __ldg(w_m0 + 0), w01 = __ldg(w_m0 + 1);
    const float w10 = __ldg(w_m0 + 2), w11 = __ldg(w_m0 + 3);
    const float wr  = __ldg(w_m1 + 0), wi = __ldg(w_m1 + 1);

    // ---- start cp.async pipeline early (depth 2, 3 buffers) ----
    float4* buf = sNF[wid];
    const float* nf_src = nbr_feats + (size_t)n * (HH * LLL * CCC);
    stage_issue(buf,      nf_src,       lane);
    stage_issue(buf + 64, nf_src + 256, lane);

    // ---- Wigner D1 + folded tables: lane h handles neighbor h (H==32) ----
    // out[0]  = w00*msg0 + w01*(D_row1 . v)
    // out[1+i]= back[i] = (D^T A D)[i] . v + w10*D[1][i]*msg0
    {
        const float* np = nbr_points + (size_t)n * 96 + lane * 3;
        float vx = __ldg(np + 0) - __ldg(s_points + n * 3 + 0);
        float vy = __ldg(np + 1) - __ldg(s_points + n * 3 + 1);
        float vz = __ldg(np + 2) - __ldg(s_points + n * 3 + 2);
        float nrm = sqrtf(vx * vx + vy * vy + vz * vz) + 1e-8f;
        float inv = 1.0f / nrm;
        vx *= inv; vy *= inv; vz *= inv;
        float cb = vz;
        float sb = sqrtf(fmaxf(1.0f - cb * cb, 0.0f));
        float rho2 = vx * vx + vy * vy;
        float ca, sa;
        if (rho2 > 1e-24f) { float ir = rsqrtf(rho2); ca = vx * ir; sa = vy * ir; }
        else               { ca = 1.0f; sa = 0.0f; }
        // D rows (D01 == 0)
        const float D00 = ca,      D02 = -sa;
        const float D10 = sb * sa, D11 = cb,  D12 = sb * ca;
        const float D20 = cb * sa, D21 = -sb, D22 = cb * ca;
        // C = A*D, A = [[wr,0,wi],[0,w11,0],[-wi,0,wr]]
        const float C0x = wr * D00 + wi * D20, C0y = wi * D21, C0z = wr * D02 + wi * D22;
        const float C1x = w11 * D10, C1y = w11 * D11, C1z = w11 * D12;
        const float C2x = wr * D20 - wi * D00, C2y = wr * D21, C2z = wr * D22 - wi * D02;
        // B = D^T C : B[i][j] = D0i*C0j + D1i*C1j + D2i*C2j  (col i of D!)
        float4* tb = &sBUT[wid][lane * 4];
        tb[0] = make_float4(w01 * D10, w01 * D11, w01 * D12, w00);
        // B[0][*]: i=0 -> D00, D10, D20
        tb[1] = make_float4(D00 * C0x + D10 * C1x + D20 * C2x,
                            D00 * C0y + D10 * C1y + D20 * C2y,
                            D00 * C0z + D10 * C1z + D20 * C2z,
                            w10 * D10);
        // B[1][*]: i=1 -> D01(=0), D11, D21
        tb[2] = make_float4(D11 * C1x + D21 * C2x,
                            D11 * C1y + D21 * C2y,
                            D11 * C1z + D21 * C2z,
                            w10 * D11);
        // B[2][*]: i=2 -> D02, D12, D22
        tb[3] = make_float4(D02 * C0x + D12 * C1x + D22 * C2x,
                            D02 * C0y + D12 * C1y + D22 * C2y,
                            D02 * C0z + D12 * C1z + D22 * C2z,
                            w10 * D12);
    }

    // 8x8 weight block per lane (cols q*8..q*8+8 for all 8 m rows), packed.
    unsigned long long wb[32];

    // ---- msg_s once (s-feature half of W_in), overlapped with async flight ----
    float msgs;
    {
        const float* base = W_in + 64 + q * 8;
        #pragma unroll
        for (int m2 = 0; m2 < 8; m2++) {
            const float4* p = reinterpret_cast<const float4*>(base + m2 * 128);
            ulonglong2 ua = pack4(__ldg(p));
            ulonglong2 ub = pack4(__ldg(p + 1));
            wb[m2 * 4 + 0] = ua.x; wb[m2 * 4 + 1] = ua.y;
            wb[m2 * 4 + 2] = ub.x; wb[m2 * 4 + 3] = ub.y;
        }
        const float4* sfp = reinterpret_cast<const float4*>(
            s_feats + (size_t)n * 256 + l * 64 + q * 8);
        ulonglong2 t0 = pack4(__ldg(sfp));
        ulonglong2 t1 = pack4(__ldg(sfp + 1));
        float vals[8];
        gemm8(wb, t0, t1, vals);
        msgs = reduce8(vals, q);
    }
    // Neighbor-half weights, loop-invariant in regs
    {
        const float* base = W_in + q * 8;
        #pragma unroll
        for (int m2 = 0; m2 < 8; m2++) {
            const float4* p = reinterpret_cast<const float4*>(base + m2 * 128);
            ulonglong2 ua = pack4(__ldg(p));
            ulonglong2 ub = pack4(__ldg(p + 1));
            wb[m2 * 4 + 0] = ua.x; wb[m2 * 4 + 1] = ua.y;
            wb[m2 * 4 + 2] = ub.x; wb[m2 * 4 + 3] = ub.y;
        }
    }
    __syncwarp();   // sBUT writes visible to all lanes before the loop

    float acc = 0.f;
    const float4* butw = sBUT[wid];

    int bcur = 0, bpre = 2;   // rotating buffer indices: consume bcur, fill bpre
    for (int h = 0; h < HH; h++) {
        if (h < HH - 1) { cpa_wait<1>(); } else { cpa_wait<0>(); }
        __syncwarp();

        // Prefetch tile h+2 into buffer bpre (freed at iter h-1; the syncwarp
        // above separates its last read from this overwrite).
        if (h + 2 < HH) {
            stage_issue(buf + bpre * 64, nf_src + (size_t)(h + 2) * 256, lane);
        }

        const float4* bp = buf + bcur * 64;
        ulonglong2 u0 = pack4(bp[lane]);        // floats [8*lane .. 8*lane+8)
        ulonglong2 u1 = pack4(bp[lane + 32]);
        float vals[8];
        gemm8(wb, u0, u1, vals);
        float msg = reduce8(vals, q) + msgs;    // lane l*8+q holds msg[l][q]

        float msg0 = __shfl_sync(FULL, msg, q);
        float r1   = __shfl_sync(FULL, msg, 8 + q);
        float r2   = __shfl_sync(FULL, msg, 16 + q);
        float r3   = __shfl_sync(FULL, msg, 24 + q);

        // Folded Wigner+mix table: l==0 -> (w01*D_row1, w00); l>=1 -> (B[l-1], w10*D[1][l-1])
        float4 g = butw[h * 4 + l];
        acc = fmaf(g.x, r1, acc);
        acc = fmaf(g.y, r2, acc);
        acc = fmaf(g.z, r3, acc);
        acc = fmaf(g.w, msg0, acc);

        bcur = (bcur == 2) ? 0 : bcur + 1;
        bpre = (bpre == 2) ? 0 : bpre + 1;
    }

    // ---- epilogue: res[n,l,o] = sum_mm acc[l][mm] * W_out[o][mm] ----
    float vals8[8];
    #pragma unroll
    for (int mm = 0; mm < 8; mm++) vals8[mm] = __shfl_sync(FULL, acc, l * 8 + mm);

    float4 o0 = make_float4(0.f, 0.f, 0.f, 0.f);
    float4 o1 = make_float4(0.f, 0.f, 0.f, 0.f);
    #pragma unroll
    for (int mm = 0; mm < 8; mm++) {
        float4 wv0 = sWoutT[mm * 16 + q];       // o = q*8..q*8+4
        float4 wv1 = sWoutT[mm * 16 + q + 8];   // o = q*8+4..q*8+8
        float v = vals8[mm];
        o0.x = fmaf(v, wv0.x, o0.x); o0.y = fmaf(v, wv0.y, o0.y);
        o0.z = fmaf(v, wv0.z, o0.z); o0.w = fmaf(v, wv0.w, o0.w);
        o1.x = fmaf(v, wv1.x, o1.x); o1.y = fmaf(v, wv1.y, o1.y);
        o1.z = fmaf(v, wv1.z, o1.z); o1.w = fmaf(v, wv1.w, o1.w);
    }
    float4* dst = reinterpret_cast<float4*>(res + (size_t)n * 256 + l * 64 + q * 8);
    dst[0] = o0;
    dst[1] = o1;
}

extern "C" void kernel_launch(void* const* d_in, const int* in_sizes, int n_in,
                              void* d_out, int out_size)
{
    const float* s_points   = (const float*)d_in[0];
    const float* nbr_points = (const float*)d_in[1];
    const float* s_feats    = (const float*)d_in[2];
    const float* nbr_feats  = (const float*)d_in[3];
    // d_in[4] = values (N,H) — unused by the reference computation
    const float* W_in       = (const float*)d_in[5];
    const float* W_out      = (const float*)d_in[6];
    const float* w_m0       = (const float*)d_in[7];
    const float* w_m1       = (const float*)d_in[8];

    const int N = in_sizes[3] / (HH * LLL * CCC);
    const int blocks = (N + 7) / 8;   // warp per n, 8 warps per block

    tp_kernel<<<blocks, 256>>>(s_points, nbr_points, s_feats, nbr_feats,
                               W_in, W_out, w_m0, w_m1, (float*)d_out, N);
}

// round 10
// speedup vs baseline: 1.0772x; 1.0772x over previous
#include <cuda_runtime.h>
#include <cstdint>
#include <cstring>

#define HH 32      // neighbors (== warp size)
#define LLL 4
#define CCC 64
#define CMID 8
#define COUT 64
#define NWARP 4    // warps (== n's) per block

// ---------------- cp.async helpers ----------------
__device__ __forceinline__ void cpa16(void* dst, const void* src) {
    unsigned d = (unsigned)__cvta_generic_to_shared(dst);
    asm volatile("cp.async.cg.shared.global [%0], [%1], 16;" :: "r"(d), "l"(src));
}
__device__ __forceinline__ void cpa_commit() { asm volatile("cp.async.commit_group;"); }
template<int K> __device__ __forceinline__ void cpa_wait() {
    asm volatile("cp.async.wait_group %0;" :: "n"(K));
}

__device__ __forceinline__ void ffma2(unsigned long long& acc,
                                      unsigned long long a, unsigned long long b) {
    asm("fma.rn.f32x2 %0, %1, %2, %0;" : "+l"(acc) : "l"(a), "l"(b));
}
__device__ __forceinline__ float2 unpack2(unsigned long long v) {
    float2 f; memcpy(&f, &v, 8); return f;
}
__device__ __forceinline__ ulonglong2 pack4(float4 v) {
    ulonglong2 u; memcpy(&u, &v, 16); return u;
}

// Stage one 1KB tile. Source chunk k (16B) -> smem slot (k>>1) + ((k&1)<<5).
// Consumer: lane i reads slots i and i+32 = floats [8i, 8i+8)  (conflict-free).
__device__ __forceinline__ void stage_issue(float4* b, const float* src, int lane) {
    const int k2 = lane + 32;
    cpa16(b + ((lane >> 1) + ((lane & 1) << 5)), src + lane * 4);
    cpa16(b + ((k2 >> 1) + ((k2 & 1) << 5)),     src + k2 * 4);
    cpa_commit();
}

// 3-round keep/send butterfly over 8-lane groups: lane (g*8+q) ends with
// sum over its group of v[q].
__device__ __forceinline__ float reduce8(const float* v, int q) {
    const unsigned FULL = 0xffffffffu;
    bool s4 = (q & 4) != 0;
    float a0 = (s4 ? v[4] : v[0]) + __shfl_xor_sync(FULL, s4 ? v[0] : v[4], 4);
    float a1 = (s4 ? v[5] : v[1]) + __shfl_xor_sync(FULL, s4 ? v[1] : v[5], 4);
    float a2 = (s4 ? v[6] : v[2]) + __shfl_xor_sync(FULL, s4 ? v[2] : v[6], 4);
    float a3 = (s4 ? v[7] : v[3]) + __shfl_xor_sync(FULL, s4 ? v[3] : v[7], 4);
    bool s2 = (q & 2) != 0;
    float b0c = (s2 ? a2 : a0) + __shfl_xor_sync(FULL, s2 ? a0 : a2, 2);
    float b1c = (s2 ? a3 : a1) + __shfl_xor_sync(FULL, s2 ? a1 : a3, 2);
    bool s1 = (q & 1) != 0;
    return (s1 ? b1c : b0c) + __shfl_xor_sync(FULL, s1 ? b0c : b1c, 1);
}

// Per-lane 8x8 GEMM panel: partials for all 8 m rows over this lane's 8 floats.
__device__ __forceinline__ void gemm8(const unsigned long long* wb,
                                      ulonglong2 u0, ulonglong2 u1, float* vals) {
    #pragma unroll
    for (int m2 = 0; m2 < 8; m2++) {
        unsigned long long am = 0ull;
        ffma2(am, u0.x, wb[m2 * 4 + 0]);
        ffma2(am, u0.y, wb[m2 * 4 + 1]);
        ffma2(am, u1.x, wb[m2 * 4 + 2]);
        ffma2(am, u1.y, wb[m2 * 4 + 3]);
        float2 f = unpack2(am);
        vals[m2] = f.x + f.y;
    }
}

__global__ __launch_bounds__(128, 4)
void tp_kernel(const float* __restrict__ s_points,
               const float* __restrict__ nbr_points,
               const float* __restrict__ s_feats,
               const float* __restrict__ nbr_feats,
               const float* __restrict__ W_in,
               const float* __restrict__ W_out,
               const float* __restrict__ w_m0,
               const float* __restrict__ w_m1,
               float* __restrict__ res, int N)
{
    __shared__ float4 sNF[NWARP][4 * 64];   // per-warp QUAD-buffered 1KB tiles (16KB)
    __shared__ float4 sBUT[NWARP][HH * 4];  // per-warp folded Wigner tables (8KB)
    __shared__ float4 sWoutT[CMID * 16];    // W_out^T, even/odd split per row (2KB)

    const int tid  = threadIdx.x;
    const int wid  = tid >> 5;
    const int lane = tid & 31;
    const int l    = lane >> 3;   // 0..3
    const int q    = lane & 7;    // 0..7
    const unsigned FULL = 0xffffffffu;

    // Stage W_out transposed + split-swizzled: value W_out[o][mm] -> row mm,
    // float4 f=o>>2 stored at slot (f>>1)+((f&1)<<3), float pos o&3.
    {
        float* wt = reinterpret_cast<float*>(sWoutT);
        for (int i = tid; i < COUT * CMID; i += 128) {
            int o = i >> 3, mm = i & 7;
            int f = o >> 2;
            int slot = (f >> 1) + ((f & 1) << 3);
            wt[mm * 64 + slot * 4 + (o & 3)] = W_out[i];
        }
    }
    __syncthreads();

    const int n = blockIdx.x * NWARP + wid;
    if (n >= N) return;   // whole warp; no block syncs below

    const float w00 = __ldg(w_m0 + 0), w01 = __ldg(w_m0 + 1);
    const float w10 = __ldg(w_m0 + 2), w11 = __ldg(w_m0 + 3);
    const float wr  = __ldg(w_m1 + 0), wi = __ldg(w_m1 + 1);

    // ---- start cp.async pipeline early (3 stages now, 4th issued in-loop) ----
    float4* buf = sNF[wid];
    const float* nf_src = nbr_feats + (size_t)n * (HH * LLL * CCC);
    stage_issue(buf,       nf_src,       lane);
    stage_issue(buf + 64,  nf_src + 256, lane);
    stage_issue(buf + 128, nf_src + 512, lane);

    // ---- Wigner D1 + folded tables: lane h handles neighbor h (H==32) ----
    // out[0]  = w00*msg0 + w01*(D_row1 . v)
    // out[1+i]= back[i] = (D^T A D)[i] . v + w10*D[1][i]*msg0
    {
        const float* np = nbr_points + (size_t)n * 96 + lane * 3;
        float vx = __ldg(np + 0) - __ldg(s_points + n * 3 + 0);
        float vy = __ldg(np + 1) - __ldg(s_points + n * 3 + 1);
        float vz = __ldg(np + 2) - __ldg(s_points + n * 3 + 2);
        float nrm = sqrtf(vx * vx + vy * vy + vz * vz) + 1e-8f;
        float inv = 1.0f / nrm;
        vx *= inv; vy *= inv; vz *= inv;
        float cb = vz;
        float sb = sqrtf(fmaxf(1.0f - cb * cb, 0.0f));
        float rho2 = vx * vx + vy * vy;
        float ca, sa;
        if (rho2 > 1e-24f) { float ir = rsqrtf(rho2); ca = vx * ir; sa = vy * ir; }
        else               { ca = 1.0f; sa = 0.0f; }
        // D rows (D01 == 0)
        const float D00 = ca,      D02 = -sa;
        const float D10 = sb * sa, D11 = cb,  D12 = sb * ca;
        const float D20 = cb * sa, D21 = -sb, D22 = cb * ca;
        // C = A*D, A = [[wr,0,wi],[0,w11,0],[-wi,0,wr]]
        const float C0x = wr * D00 + wi * D20, C0y = wi * D21, C0z = wr * D02 + wi * D22;
        const float C1x = w11 * D10, C1y = w11 * D11, C1z = w11 * D12;
        const float C2x = wr * D20 - wi * D00, C2y = wr * D21, C2z = wr * D22 - wi * D02;
        // B = D^T C : B[i][j] = D0i*C0j + D1i*C1j + D2i*C2j  (col i of D)
        float4* tb = &sBUT[wid][lane * 4];
        tb[0] = make_float4(w01 * D10, w01 * D11, w01 * D12, w00);
        // B[0][*]: i=0 -> D00, D10, D20
        tb[1] = make_float4(D00 * C0x + D10 * C1x + D20 * C2x,
                            D00 * C0y + D10 * C1y + D20 * C2y,
                            D00 * C0z + D10 * C1z + D20 * C2z,
                            w10 * D10);
        // B[1][*]: i=1 -> D01(=0), D11, D21
        tb[2] = make_float4(D11 * C1x + D21 * C2x,
                            D11 * C1y + D21 * C2y,
                            D11 * C1z + D21 * C2z,
                            w10 * D11);
        // B[2][*]: i=2 -> D02, D12, D22
        tb[3] = make_float4(D02 * C0x + D12 * C1x + D22 * C2x,
                            D02 * C0y + D12 * C1y + D22 * C2y,
                            D02 * C0z + D12 * C1z + D22 * C2z,
                            w10 * D12);
    }

    // 8x8 weight block per lane (cols q*8..q*8+8 for all 8 m rows), packed.
    unsigned long long wb[32];

    // ---- msg_s once (s-feature half of W_in), overlapped with async flight ----
    float msgs;
    {
        const float* base = W_in + 64 + q * 8;
        #pragma unroll
        for (int m2 = 0; m2 < 8; m2++) {
            const float4* p = reinterpret_cast<const float4*>(base + m2 * 128);
            ulonglong2 ua = pack4(__ldg(p));
            ulonglong2 ub = pack4(__ldg(p + 1));
            wb[m2 * 4 + 0] = ua.x; wb[m2 * 4 + 1] = ua.y;
            wb[m2 * 4 + 2] = ub.x; wb[m2 * 4 + 3] = ub.y;
        }
        const float4* sfp = reinterpret_cast<const float4*>(
            s_feats + (size_t)n * 256 + l * 64 + q * 8);
        ulonglong2 t0 = pack4(__ldg(sfp));
        ulonglong2 t1 = pack4(__ldg(sfp + 1));
        float vals[8];
        gemm8(wb, t0, t1, vals);
        msgs = reduce8(vals, q);
    }
    // Neighbor-half weights, loop-invariant in regs
    {
        const float* base = W_in + q * 8;
        #pragma unroll
        for (int m2 = 0; m2 < 8; m2++) {
            const float4* p = reinterpret_cast<const float4*>(base + m2 * 128);
            ulonglong2 ua = pack4(__ldg(p));
            ulonglong2 ub = pack4(__ldg(p + 1));
            wb[m2 * 4 + 0] = ua.x; wb[m2 * 4 + 1] = ua.y;
            wb[m2 * 4 + 2] = ub.x; wb[m2 * 4 + 3] = ub.y;
        }
    }
    __syncwarp();   // sBUT writes visible to all lanes before the loop

    float acc = 0.f;
    const float4* butw = sBUT[wid];

    for (int h = 0; h < HH; h++) {
        // Issue stage h+3 BEFORE waiting: its buffer (h+3)&3 == (h-1)&3 was
        // last read at iteration h-1, separated by that iteration's syncwarp.
        // This keeps 4 groups in flight while we wait for stage h.
        if (h + 3 < HH) {
            stage_issue(buf + ((h + 3) & 3) * 64, nf_src + (size_t)(h + 3) * 256, lane);
        }
        // Pending groups: h<=28 -> 4 (h..h+3), h=29 -> 3, h=30 -> 2, h=31 -> 1.
        if (h <= HH - 4)      { cpa_wait<3>(); }
        else if (h == HH - 3) { cpa_wait<2>(); }
        else if (h == HH - 2) { cpa_wait<1>(); }
        else                  { cpa_wait<0>(); }
        __syncwarp();

        const float4* bp = buf + (h & 3) * 64;
        ulonglong2 u0 = pack4(bp[lane]);        // floats [8*lane .. 8*lane+8)
        ulonglong2 u1 = pack4(bp[lane + 32]);
        float vals[8];
        gemm8(wb, u0, u1, vals);
        float msg = reduce8(vals, q) + msgs;    // lane l*8+q holds msg[l][q]

        float msg0 = __shfl_sync(FULL, msg, q);
        float r1   = __shfl_sync(FULL, msg, 8 + q);
        float r2   = __shfl_sync(FULL, msg, 16 + q);
        float r3   = __shfl_sync(FULL, msg, 24 + q);

        // Folded Wigner+mix table: l==0 -> (w01*D_row1, w00); l>=1 -> (B[l-1], w10*D[1][l-1])
        float4 g = butw[h * 4 + l];
        acc = fmaf(g.x, r1, acc);
        acc = fmaf(g.y, r2, acc);
        acc = fmaf(g.z, r3, acc);
        acc = fmaf(g.w, msg0, acc);
    }

    // ---- epilogue: res[n,l,o] = sum_mm acc[l][mm] * W_out[o][mm] ----
    float vals8[8];
    #pragma unroll
    for (int mm = 0; mm < 8; mm++) vals8[mm] = __shfl_sync(FULL, acc, l * 8 + mm);

    float4 o0 = make_float4(0.f, 0.f, 0.f, 0.f);
    float4 o1 = make_float4(0.f, 0.f, 0.f, 0.f);
    #pragma unroll
    for (int mm = 0; mm < 8; mm++) {
        float4 wv0 = sWoutT[mm * 16 + q];       // o = q*8..q*8+4
        float4 wv1 = sWoutT[mm * 16 + q + 8];   // o = q*8+4..q*8+8
        float v = vals8[mm];
        o0.x = fmaf(v, wv0.x, o0.x); o0.y = fmaf(v, wv0.y, o0.y);
        o0.z = fmaf(v, wv0.z, o0.z); o0.w = fmaf(v, wv0.w, o0.w);
        o1.x = fmaf(v, wv1.x, o1.x); o1.y = fmaf(v, wv1.y, o1.y);
        o1.z = fmaf(v, wv1.z, o1.z); o1.w = fmaf(v, wv1.w, o1.w);
    }
    float4* dst = reinterpret_cast<float4*>(res + (size_t)n * 256 + l * 64 + q * 8);
    dst[0] = o0;
    dst[1] = o1;
}

extern "C" void kernel_launch(void* const* d_in, const int* in_sizes, int n_in,
                              void* d_out, int out_size)
{
    const float* s_points   = (const float*)d_in[0];
    const float* nbr_points = (const float*)d_in[1];
    const float* s_feats    = (const float*)d_in[2];
    const float* nbr_feats  = (const float*)d_in[3];
    // d_in[4] = values (N,H) — unused by the reference computation
    const float* W_in       = (const float*)d_in[5];
    const float* W_out      = (const float*)d_in[6];
    const float* w_m0       = (const float*)d_in[7];
    const float* w_m1       = (const float*)d_in[8];

    const int N = in_sizes[3] / (HH * LLL * CCC);
    const int blocks = (N + NWARP - 1) / NWARP;   // warp per n, 4 warps per block

    tp_kernel<<<blocks, NWARP * 32>>>(s_points, nbr_points, s_feats, nbr_feats,
                                      W_in, W_out, w_m0, w_m1, (float*)d_out, N);
}

// round 12
// speedup vs baseline: 1.1238x; 1.0433x over previous
#include <cuda_runtime.h>
#include <cstdint>
#include <cstring>

#define HH 32      // neighbors (== warp size)
#define LLL 4
#define CCC 64
#define CMID 8
#define COUT 64
#define NWARP 4    // warps (== n's) per block
#define NBUF 6     // tile buffers per warp

// ---------------- cp.async helpers ----------------
__device__ __forceinline__ void cpa16(void* dst, const void* src) {
    unsigned d = (unsigned)__cvta_generic_to_shared(dst);
    asm volatile("cp.async.cg.shared.global [%0], [%1], 16;" :: "r"(d), "l"(src));
}
__device__ __forceinline__ void cpa_commit() { asm volatile("cp.async.commit_group;"); }
template<int K> __device__ __forceinline__ void cpa_wait() {
    asm volatile("cp.async.wait_group %0;" :: "n"(K));
}

__device__ __forceinline__ void ffma2(unsigned long long& acc,
                                      unsigned long long a, unsigned long long b) {
    asm("fma.rn.f32x2 %0, %1, %2, %0;" : "+l"(acc) : "l"(a), "l"(b));
}
__device__ __forceinline__ float2 unpack2(unsigned long long v) {
    float2 f; memcpy(&f, &v, 8); return f;
}
__device__ __forceinline__ ulonglong2 pack4(float4 v) {
    ulonglong2 u; memcpy(&u, &v, 16); return u;
}

// Stage one 1KB tile. Source chunk k (16B) -> smem slot (k>>1) + ((k&1)<<5).
// Consumer: lane i reads slots i and i+32 = floats [8i, 8i+8)  (conflict-free).
__device__ __forceinline__ void stage_issue(float4* b, const float* src, int lane) {
    const int k2 = lane + 32;
    cpa16(b + ((lane >> 1) + ((lane & 1) << 5)), src + lane * 4);
    cpa16(b + ((k2 >> 1) + ((k2 & 1) << 5)),     src + k2 * 4);
    cpa_commit();
}

// Dual 8-lane butterfly reduction, A/B chains interleaved so B's shuffle
// latency hides A's. Lane (g*8+q) ends with sum over its group of v[q].
__device__ __forceinline__ void reduce8x2(const float* va, const float* vb, int q,
                                          float& outA, float& outB) {
    const unsigned FULL = 0xffffffffu;
    bool s4 = (q & 4) != 0;
    float a0 = (s4 ? va[4] : va[0]) + __shfl_xor_sync(FULL, s4 ? va[0] : va[4], 4);
    float b0 = (s4 ? vb[4] : vb[0]) + __shfl_xor_sync(FULL, s4 ? vb[0] : vb[4], 4);
    float a1 = (s4 ? va[5] : va[1]) + __shfl_xor_sync(FULL, s4 ? va[1] : va[5], 4);
    float b1 = (s4 ? vb[5] : vb[1]) + __shfl_xor_sync(FULL, s4 ? vb[1] : vb[5], 4);
    float a2 = (s4 ? va[6] : va[2]) + __shfl_xor_sync(FULL, s4 ? va[2] : va[6], 4);
    float b2 = (s4 ? vb[6] : vb[2]) + __shfl_xor_sync(FULL, s4 ? vb[2] : vb[6], 4);
    float a3 = (s4 ? va[7] : va[3]) + __shfl_xor_sync(FULL, s4 ? va[3] : va[7], 4);
    float b3 = (s4 ? vb[7] : vb[3]) + __shfl_xor_sync(FULL, s4 ? vb[3] : vb[7], 4);
    bool s2 = (q & 2) != 0;
    float aa0 = (s2 ? a2 : a0) + __shfl_xor_sync(FULL, s2 ? a0 : a2, 2);
    float bb0 = (s2 ? b2 : b0) + __shfl_xor_sync(FULL, s2 ? b0 : b2, 2);
    float aa1 = (s2 ? a3 : a1) + __shfl_xor_sync(FULL, s2 ? a1 : a3, 2);
    float bb1 = (s2 ? b3 : b1) + __shfl_xor_sync(FULL, s2 ? b1 : b3, 2);
    bool s1 = (q & 1) != 0;
    outA = (s1 ? aa1 : aa0) + __shfl_xor_sync(FULL, s1 ? aa0 : aa1, 1);
    outB = (s1 ? bb1 : bb0) + __shfl_xor_sync(FULL, s1 ? bb0 : bb1, 1);
}

// Single-tile variant (prologue msg_s only)
__device__ __forceinline__ float reduce8(const float* v, int q) {
    const unsigned FULL = 0xffffffffu;
    bool s4 = (q & 4) != 0;
    float a0 = (s4 ? v[4] : v[0]) + __shfl_xor_sync(FULL, s4 ? v[0] : v[4], 4);
    float a1 = (s4 ? v[5] : v[1]) + __shfl_xor_sync(FULL, s4 ? v[1] : v[5], 4);
    float a2 = (s4 ? v[6] : v[2]) + __shfl_xor_sync(FULL, s4 ? v[2] : v[6], 4);
    float a3 = (s4 ? v[7] : v[3]) + __shfl_xor_sync(FULL, s4 ? v[3] : v[7], 4);
    bool s2 = (q & 2) != 0;
    float b0c = (s2 ? a2 : a0) + __shfl_xor_sync(FULL, s2 ? a0 : a2, 2);
    float b1c = (s2 ? a3 : a1) + __shfl_xor_sync(FULL, s2 ? a1 : a3, 2);
    bool s1 = (q & 1) != 0;
    return (s1 ? b1c : b0c) + __shfl_xor_sync(FULL, s1 ? b0c : b1c, 1);
}

// Per-lane 8x8 GEMM panel: partials for all 8 m rows over this lane's 8 floats.
__device__ __forceinline__ void gemm8(const unsigned long long* wb,
                                      ulonglong2 u0, ulonglong2 u1, float* vals) {
    #pragma unroll
    for (int m2 = 0; m2 < 8; m2++) {
        unsigned long long am = 0ull;
        ffma2(am, u0.x, wb[m2 * 4 + 0]);
        ffma2(am, u0.y, wb[m2 * 4 + 1]);
        ffma2(am, u1.x, wb[m2 * 4 + 2]);
        ffma2(am, u1.y, wb[m2 * 4 + 3]);
        float2 f = unpack2(am);
        vals[m2] = f.x + f.y;
    }
}

__global__ __launch_bounds__(128, 4)
void tp_kernel(const float* __restrict__ s_points,
               const float* __restrict__ nbr_points,
               const float* __restrict__ s_feats,
               const float* __restrict__ nbr_feats,
               const float* __restrict__ W_in,
               const float* __restrict__ W_out,
               const float* __restrict__ w_m0,
               const float* __restrict__ w_m1,
               float* __restrict__ res, int N)
{
    __shared__ float4 sNF[NWARP][NBUF * 64]; // per-warp 6x1KB tile ring (24KB)
    __shared__ float4 sBUT[NWARP][HH * 4];   // per-warp folded Wigner tables (8KB)
    __shared__ float4 sWoutT[CMID * 16];     // W_out^T, even/odd split (2KB)

    const int tid  = threadIdx.x;
    const int wid  = tid >> 5;
    const int lane = tid & 31;
    const int l    = lane >> 3;   // 0..3
    const int q    = lane & 7;    // 0..7
    const unsigned FULL = 0xffffffffu;

    // Stage W_out transposed + split-swizzled.
    {
        float* wt = reinterpret_cast<float*>(sWoutT);
        for (int i = tid; i < COUT * CMID; i += 128) {
            int o = i >> 3, mm = i & 7;
            int f = o >> 2;
            int slot = (f >> 1) + ((f & 1) << 3);
            wt[mm * 64 + slot * 4 + (o & 3)] = W_out[i];
        }
    }
    __syncthreads();

    const int n = blockIdx.x * NWARP + wid;
    if (n >= N) return;   // whole warp; no block syncs below

    const float w00 = __ldg(w_m0 + 0), w01 = __ldg(w_m0 + 1);
    const float w10 = __ldg(w_m0 + 2), w11 = __ldg(w_m0 + 3);
    const float wr  = __ldg(w_m1 + 0), wi = __ldg(w_m1 + 1);

    // ---- start cp.async pipeline: stages 0..3 into buffers 0..3 ----
    float4* buf = sNF[wid];
    const float* nf_src = nbr_feats + (size_t)n * (HH * LLL * CCC);
    stage_issue(buf,       nf_src,       lane);
    stage_issue(buf + 64,  nf_src + 256, lane);
    stage_issue(buf + 128, nf_src + 512, lane);
    stage_issue(buf + 192, nf_src + 768, lane);

    // ---- Wigner D1 + folded tables: lane h handles neighbor h (H==32) ----
    // out[0]  = w00*msg0 + w01*(D_row1 . v)
    // out[1+i]= (D^T A D)[i] . v + w10*D[1][i]*msg0
    {
        const float* np = nbr_points + (size_t)n * 96 + lane * 3;
        float vx = __ldg(np + 0) - __ldg(s_points + n * 3 + 0);
        float vy = __ldg(np + 1) - __ldg(s_points + n * 3 + 1);
        float vz = __ldg(np + 2) - __ldg(s_points + n * 3 + 2);
        float nrm = sqrtf(vx * vx + vy * vy + vz * vz) + 1e-8f;
        float inv = 1.0f / nrm;
        vx *= inv; vy *= inv; vz *= inv;
        float cb = vz;
        float sb = sqrtf(fmaxf(1.0f - cb * cb, 0.0f));
        float rho2 = vx * vx + vy * vy;
        float ca, sa;
        if (rho2 > 1e-24f) { float ir = rsqrtf(rho2); ca = vx * ir; sa = vy * ir; }
        else               { ca = 1.0f; sa = 0.0f; }
        const float D00 = ca,      D02 = -sa;                 // D01 = 0
        const float D10 = sb * sa, D11 = cb,  D12 = sb * ca;
        const float D20 = cb * sa, D21 = -sb, D22 = cb * ca;
        // C = A*D, A = [[wr,0,wi],[0,w11,0],[-wi,0,wr]]
        const float C0x = wr * D00 + wi * D20, C0y = wi * D21, C0z = wr * D02 + wi * D22;
        const float C1x = w11 * D10, C1y = w11 * D11, C1z = w11 * D12;
        const float C2x = wr * D20 - wi * D00, C2y = wr * D21, C2z = wr * D22 - wi * D02;
        float4* tb = &sBUT[wid][lane * 4];
        tb[0] = make_float4(w01 * D10, w01 * D11, w01 * D12, w00);
        tb[1] = make_float4(D00 * C0x + D10 * C1x + D20 * C2x,
                            D00 * C0y + D10 * C1y + D20 * C2y,
                            D00 * C0z + D10 * C1z + D20 * C2z,
                            w10 * D10);
        tb[2] = make_float4(D11 * C1x + D21 * C2x,
                            D11 * C1y + D21 * C2y,
                            D11 * C1z + D21 * C2z,
                            w10 * D11);
        tb[3] = make_float4(D02 * C0x + D12 * C1x + D22 * C2x,
                            D02 * C0y + D12 * C1y + D22 * C2y,
                            D02 * C0z + D12 * C1z + D22 * C2z,
                            w10 * D12);
    }

    // 8x8 weight block per lane (cols q*8..q*8+8 for all 8 m rows), packed.
    unsigned long long wb[32];

    // ---- msg_s once (s-feature half of W_in), overlapped with async flight ----
    float msgs;
    {
        const float* base = W_in + 64 + q * 8;
        #pragma unroll
        for (int m2 = 0; m2 < 8; m2++) {
            const float4* p = reinterpret_cast<const float4*>(base + m2 * 128);
            ulonglong2 ua = pack4(__ldg(p));
            ulonglong2 ub = pack4(__ldg(p + 1));
            wb[m2 * 4 + 0] = ua.x; wb[m2 * 4 + 1] = ua.y;
            wb[m2 * 4 + 2] = ub.x; wb[m2 * 4 + 3] = ub.y;
        }
        const float4* sfp = reinterpret_cast<const float4*>(
            s_feats + (size_t)n * 256 + l * 64 + q * 8);
        ulonglong2 t0 = pack4(__ldg(sfp));
        ulonglong2 t1 = pack4(__ldg(sfp + 1));
        float vals[8];
        gemm8(wb, t0, t1, vals);
        msgs = reduce8(vals, q);
    }
    // Neighbor-half weights, loop-invariant in regs
    {
        const float* base = W_in + q * 8;
        #pragma unroll
        for (int m2 = 0; m2 < 8; m2++) {
            const float4* p = reinterpret_cast<const float4*>(base + m2 * 128);
            ulonglong2 ua = pack4(__ldg(p));
            ulonglong2 ub = pack4(__ldg(p + 1));
            wb[m2 * 4 + 0] = ua.x; wb[m2 * 4 + 1] = ua.y;
            wb[m2 * 4 + 2] = ub.x; wb[m2 * 4 + 3] = ub.y;
        }
    }
    __syncwarp();   // sBUT writes visible to all lanes before the loop

    float acc = 0.f;
    const float4* butw = sBUT[wid];

    // Process tile PAIRS: one wait + one syncwarp per 2 tiles; the two
    // gemm/reduce chains interleave to double per-warp ILP.
    int bA = 0;          // buffer of stage hp; pair partner is bA+1 (never wraps mid-pair)
    int bP = 4;          // buffer of stage hp+4
    for (int hp = 0; hp < HH; hp += 2) {
        // Entering: pending groups = stages hp..hp+3. Complete hp, hp+1.
        if (hp < HH - 2) { cpa_wait<2>(); } else { cpa_wait<0>(); }
        __syncwarp();

        // Refill: stages hp+4, hp+5 into buffers freed at iteration hp-2
        // (their last reads are separated by the syncwarp above).
        if (hp + 4 < HH) {
            stage_issue(buf + bP * 64, nf_src + (size_t)(hp + 4) * 256, lane);
            int bP2 = (bP + 1 == NBUF) ? 0 : bP + 1;
            stage_issue(buf + bP2 * 64, nf_src + (size_t)(hp + 5) * 256, lane);
        }

        // ---- tile A (stage hp) ----
        const float4* bpA = buf + bA * 64;
        ulonglong2 u0 = pack4(bpA[lane]);
        ulonglong2 u1 = pack4(bpA[lane + 32]);
        float valsA[8];
        gemm8(wb, u0, u1, valsA);
        // ---- tile B (stage hp+1) ----
        const float4* bpB = bpA + 64;
        u0 = pack4(bpB[lane]);
        u1 = pack4(bpB[lane + 32]);
        float valsB[8];
        gemm8(wb, u0, u1, valsB);

        float mA, mB;
        reduce8x2(valsA, valsB, q, mA, mB);
        float msgA = mA + msgs;
        float msgB = mB + msgs;

        // broadcasts (A/B interleaved; independent chains)
        float msg0A = __shfl_sync(FULL, msgA, q);
        float msg0B = __shfl_sync(FULL, msgB, q);
        float r1A   = __shfl_sync(FULL, msgA, 8 + q);
        float r1B   = __shfl_sync(FULL, msgB, 8 + q);
        float r2A   = __shfl_sync(FULL, msgA, 16 + q);
        float r2B   = __shfl_sync(FULL, msgB, 16 + q);
        float r3A   = __shfl_sync(FULL, msgA, 24 + q);
        float r3B   = __shfl_sync(FULL, msgB, 24 + q);

        float4 gA = butw[hp * 4 + l];
        float4 gB = butw[hp * 4 + 4 + l];
        acc = fmaf(gA.x, r1A, acc);
        acc = fmaf(gA.y, r2A, acc);
        acc = fmaf(gA.z, r3A, acc);
        acc = fmaf(gA.w, msg0A, acc);
        acc = fmaf(gB.x, r1B, acc);
        acc = fmaf(gB.y, r2B, acc);
        acc = fmaf(gB.z, r3B, acc);
        acc = fmaf(gB.w, msg0B, acc);

        bA += 2; if (bA >= NBUF) bA -= NBUF;
        bP += 2; if (bP >= NBUF) bP -= NBUF;
    }

    // ---- epilogue: res[n,l,o] = sum_mm acc[l][mm] * W_out[o][mm] ----
    float vals8[8];
    #pragma unroll
    for (int mm = 0; mm < 8; mm++) vals8[mm] = __shfl_sync(FULL, acc, l * 8 + mm);

    float4 o0 = make_float4(0.f, 0.f, 0.f, 0.f);
    float4 o1 = make_float4(0.f, 0.f, 0.f, 0.f);
    #pragma unroll
    for (int mm = 0; mm < 8; mm++) {
        float4 wv0 = sWoutT[mm * 16 + q];
        float4 wv1 = sWoutT[mm * 16 + q + 8];
        float v = vals8[mm];
        o0.x = fmaf(v, wv0.x, o0.x); o0.y = fmaf(v, wv0.y, o0.y);
        o0.z = fmaf(v, wv0.z, o0.z); o0.w = fmaf(v, wv0.w, o0.w);
        o1.x = fmaf(v, wv1.x, o1.x); o1.y = fmaf(v, wv1.y, o1.y);
        o1.z = fmaf(v, wv1.z, o1.z); o1.w = fmaf(v, wv1.w, o1.w);
    }
    float4* dst = reinterpret_cast<float4*>(res + (size_t)n * 256 + l * 64 + q * 8);
    dst[0] = o0;
    dst[1] = o1;
}

extern "C" void kernel_launch(void* const* d_in, const int* in_sizes, int n_in,
                              void* d_out, int out_size)
{
    const float* s_points   = (const float*)d_in[0];
    const float* nbr_points = (const float*)d_in[1];
    const float* s_feats    = (const float*)d_in[2];
    const float* nbr_feats  = (const float*)d_in[3];
    // d_in[4] = values (N,H) — unused by the reference computation
    const float* W_in       = (const float*)d_in[5];
    const float* W_out      = (const float*)d_in[6];
    const float* w_m0       = (const float*)d_in[7];
    const float* w_m1       = (const float*)d_in[8];

    const int N = in_sizes[3] / (HH * LLL * CCC);
    const int blocks = (N + NWARP - 1) / NWARP;   // warp per n, 4 warps per block

    tp_kernel<<<blocks, NWARP * 32>>>(s_points, nbr_points, s_feats, nbr_feats,
                                      W_in, W_out, w_m0, w_m1, (float*)d_out, N);
}